// round 12
// baseline (speedup 1.0000x reference)
#include <cuda_runtime.h>

// EHD layer v10b (v10 with alignment fix):
//   3x3 conv (8 filters) -> argmax+thresh -> byte-packed one-hot ->
//   separable 5x5 box sum -> magic-number unpack -> out[B,9,1018,1018].
//
// v10b vs v9:
//  - stage D on column QUADS (half the LDS per px, amortized addressing),
//    but stores are 2x float2 per bin: odd output rows are only 8B-aligned
//    (OUT_W=1018 -> row offset = 2 mod 4 floats), so STG.128 would fault.
//  - launch_bounds(256,6): 42-reg cap -> 6 CTAs/SM (48 warps).

#define NOR    8
#define NBINS  9
#define OUT_H  1018
#define OUT_W  1018
#define THRESH 0.9f

#define T   28            // output tile
#define IT  32            // index tile (T+4)

#define NTHREADS 256

typedef unsigned long long u64;

__constant__ float c_masks[NOR * 9];

__device__ __forceinline__ float cnt_scale(unsigned word, int byte_sel) {
    // word's byte[byte_sel] = count in 0..25 -> count * fl(1/25), exact
    const unsigned bits = __byte_perm(word, 0x4B000000u, 0x7440 | byte_sel);
    return fmaf(__int_as_float(bits), (1.0f / 25.0f),
                -(8388608.0f * (1.0f / 25.0f)));
}

__global__ __launch_bounds__(NTHREADS, 6)
void ehd_fused_kernel(const float* __restrict__ x,
                      float* __restrict__ out)
{
    __shared__ u64 s_h[IT][36];   // horizontal 5-sums (16B-aligned quad cols)

    const int tid  = threadIdx.x;
    const int lane = tid & 31;
    const int ox   = blockIdx.x * T;
    const int oy   = blockIdx.y * T;
    const int b    = blockIdx.z;

    const int r  = tid >> 3;          // index row within tile (0..31)
    const int c0 = (tid & 7) << 2;    // index col group (0,4,...,28)
    const int gx = ox + c0;           // global col of first px (mult of 4)
    const int gy = oy + r;            // global row of index px

    const float* xb = x + (size_t)b * (1024 * 1024);

    // ---- stage A: load 3x6 input window straight from global ----
    float w[3][6];
    if (ox + 34 <= 1024 && oy + 34 <= 1024) {
        // fast path: whole 34x34 input footprint in-bounds (36/37 tiles each way)
#pragma unroll
        for (int j = 0; j < 3; j++) {
            const float* row = xb + (gy + j) * 1024 + gx;
            const float4 a = *(const float4*)row;       // gx multiple of 4
            const float2 bb = *(const float2*)(row + 4);
            w[j][0] = a.x; w[j][1] = a.y; w[j][2] = a.z;
            w[j][3] = a.w; w[j][4] = bb.x; w[j][5] = bb.y;
        }
    } else {
        // slow path (edge tiles): per-element predicated, zero-fill OOB.
        // OOB zeros only feed index px whose outputs are clipped below.
#pragma unroll
        for (int j = 0; j < 3; j++) {
            const int yy = gy + j;
            const bool yv = (yy < 1024);
            const float* row = xb + yy * 1024 + gx;
#pragma unroll
            for (int k = 0; k < 6; k++)
                w[j][k] = (yv && (gx + k < 1024)) ? row[k] : 0.0f;
        }
    }

    // ---- stage B: conv (8 filters) + argmax + threshold, 4 horizontal px ----
    float best[4];
    int   bi[4];
#pragma unroll
    for (int q = 0; q < 4; q++) { best[q] = -3.4e38f; bi[q] = 0; }

#pragma unroll
    for (int f = 0; f < NOR; f++) {
        const float m0 = c_masks[f * 9 + 0], m1 = c_masks[f * 9 + 1], m2 = c_masks[f * 9 + 2];
        const float m3 = c_masks[f * 9 + 3], m4 = c_masks[f * 9 + 4], m5 = c_masks[f * 9 + 5];
        const float m6 = c_masks[f * 9 + 6], m7 = c_masks[f * 9 + 7], m8 = c_masks[f * 9 + 8];
#pragma unroll
        for (int q = 0; q < 4; q++) {
            float acc = w[0][q] * m0;
            acc = fmaf(w[0][q + 1], m1, acc);
            acc = fmaf(w[0][q + 2], m2, acc);
            acc = fmaf(w[1][q    ], m3, acc);
            acc = fmaf(w[1][q + 1], m4, acc);
            acc = fmaf(w[1][q + 2], m5, acc);
            acc = fmaf(w[2][q    ], m6, acc);
            acc = fmaf(w[2][q + 1], m7, acc);
            acc = fmaf(w[2][q + 2], m8, acc);
            // strict > keeps FIRST max (jnp.argmax tie-break)
            if (acc > best[q]) { best[q] = acc; bi[q] = f; }
        }
    }

    // byte-packed one-hot: bins 0..7 -> one byte of a u64; bin 8 implicit
    u64 oh[4];
#pragma unroll
    for (int q = 0; q < 4; q++) {
        const int idx = (best[q] < THRESH) ? NOR : bi[q];
        oh[q] = (idx < NOR) ? (1ULL << (idx << 3)) : 0ULL;
    }

    // ---- stage C: horizontal 5-tap via shfl (neighbor quad = lane+1) ----
    const bool has_nbr = ((lane & 7) != 7);
    u64 n[4];
#pragma unroll
    for (int q = 0; q < 4; q++) {
        const u64 t = __shfl_down_sync(0xFFFFFFFFu, oh[q], 1);
        n[q] = has_nbr ? t : 0ULL;
    }
    const u64 h0 = oh[0] + oh[1] + oh[2] + oh[3] + n[0];
    const u64 h1 = h0 - oh[0] + n[1];
    const u64 h2 = h1 - oh[1] + n[2];
    const u64 h3 = h2 - oh[2] + n[3];
    {
        ulonglong2* dst = (ulonglong2*)&s_h[r][c0];
        dst[0] = make_ulonglong2(h0, h1);
        dst[1] = make_ulonglong2(h2, h3);
    }
    __syncthreads();   // the only barrier

    // ---- stage D: vertical 5-tap on column QUADS, unpack, 2x float2/bin ----
    // unit: rr = tid>>3 (28 rows used), qq = tid&7 (7 quads used). Single pass.
    // float2 (8B) stores: row offset (2*oyy mod 4) and oxx are both even, so
    // 8B alignment always holds; 16B does NOT (odd rows) -> no float4.
    {
        const int rr = tid >> 3;
        const int qq = tid & 7;
        const int cc = qq << 2;
        const int oyy = oy + rr, oxx = ox + cc;
        if (rr < T && qq < 7 && oyy < OUT_H && oxx < OUT_W) {
            u64 v[4] = {0ULL, 0ULL, 0ULL, 0ULL};
#pragma unroll
            for (int j = 0; j < 5; j++) {
                const ulonglong2 a  = *(const ulonglong2*)&s_h[rr + j][cc];
                const ulonglong2 bq = *(const ulonglong2*)&s_h[rr + j][cc + 2];
                v[0] += a.x; v[1] += a.y; v[2] += bq.x; v[3] += bq.y;
            }
            unsigned lo[4], hi[4];
#pragma unroll
            for (int q = 0; q < 4; q++) { lo[q] = (unsigned)v[q]; hi[q] = (unsigned)(v[q] >> 32); }

            const size_t plane = (size_t)OUT_H * OUT_W;
            float* p = out + (size_t)b * NBINS * plane + (size_t)oyy * OUT_W + oxx;

            if (oxx + 3 < OUT_W) {
                // fast path: full quad in-bounds -> 18x STG.64
#pragma unroll
                for (int bin = 0; bin < 8; bin++) {
                    float2 oa, ob2;
                    oa.x  = cnt_scale((bin < 4) ? lo[0] : hi[0], bin & 3);
                    oa.y  = cnt_scale((bin < 4) ? lo[1] : hi[1], bin & 3);
                    ob2.x = cnt_scale((bin < 4) ? lo[2] : hi[2], bin & 3);
                    ob2.y = cnt_scale((bin < 4) ? lo[3] : hi[3], bin & 3);
                    float* q8 = p + (size_t)bin * plane;
                    *(float2*)q8       = oa;
                    *(float2*)(q8 + 2) = ob2;
                }
                float2 o8a, o8b;
                o8a.x = cnt_scale(25u - __dp4a(lo[0], 0x01010101u, __dp4a(hi[0], 0x01010101u, 0u)), 0);
                o8a.y = cnt_scale(25u - __dp4a(lo[1], 0x01010101u, __dp4a(hi[1], 0x01010101u, 0u)), 0);
                o8b.x = cnt_scale(25u - __dp4a(lo[2], 0x01010101u, __dp4a(hi[2], 0x01010101u, 0u)), 0);
                o8b.y = cnt_scale(25u - __dp4a(lo[3], 0x01010101u, __dp4a(hi[3], 0x01010101u, 0u)), 0);
                float* q8 = p + (size_t)8 * plane;
                *(float2*)q8       = o8a;
                *(float2*)(q8 + 2) = o8b;
            } else {
                // edge quad (last column tile only): per-element
#pragma unroll
                for (int q = 0; q < 4; q++) {
                    if (oxx + q < OUT_W) {
#pragma unroll
                        for (int bin = 0; bin < 8; bin++)
                            p[(size_t)bin * plane + q] =
                                cnt_scale((bin < 4) ? lo[q] : hi[q], bin & 3);
                        const unsigned s8 =
                            __dp4a(lo[q], 0x01010101u, __dp4a(hi[q], 0x01010101u, 0u));
                        p[(size_t)8 * plane + q] = cnt_scale(25u - s8, 0);
                    }
                }
            }
        }
    }
}

extern "C" void kernel_launch(void* const* d_in, const int* in_sizes, int n_in,
                              void* d_out, int out_size)
{
    const float* x     = (const float*)d_in[0];   // [B,1,1024,1024]
    const float* masks = (const float*)d_in[1];   // [8,1,3,3]
    float* out = (float*)d_out;                   // [B,9,1018,1018]

    const int batch = in_sizes[0] / (1024 * 1024);

    // masks -> constant bank (device-to-device async copy: graph-capturable)
    cudaMemcpyToSymbolAsync(c_masks, masks, NOR * 9 * sizeof(float), 0,
                            cudaMemcpyDeviceToDevice);

    dim3 grid((OUT_W + T - 1) / T, (OUT_H + T - 1) / T, batch);
    ehd_fused_kernel<<<grid, NTHREADS>>>(x, out);
}

// round 13
// speedup vs baseline: 1.2520x; 1.2520x over previous
#include <cuda_runtime.h>

// EHD layer v11 (= v9 + shfl window borrow):
//   3x3 conv (8 filters) -> argmax+thresh -> byte-packed one-hot ->
//   separable 5x5 box sum -> magic-number unpack -> out[B,9,1018,1018].
//
// v11 vs v9 (the 196us best):
//  - stage A fast path loads only its own quad (3x LDG.128); window cols
//    4..5 come from lane+1 via shfl (they are lane+1's cols 0..1), with a
//    predicated LDG.64 fallback for lanes at the col-group edge (lane&7==7,
//    where lane+1 is a different row). ~30% less L1 read traffic.
//  - everything else identical to v9: regs 48 @ 5 CTAs/SM, one barrier,
//    pair-column stage D with float2 stores.

#define NOR    8
#define NBINS  9
#define OUT_H  1018
#define OUT_W  1018
#define THRESH 0.9f

#define T   28            // output tile
#define IT  32            // index tile (T+4)

#define NTHREADS 256

typedef unsigned long long u64;

__constant__ float c_masks[NOR * 9];

__device__ __forceinline__ float cnt_scale(unsigned word, int byte_sel) {
    // word's byte[byte_sel] = count in 0..25 -> count * fl(1/25), exact
    const unsigned bits = __byte_perm(word, 0x4B000000u, 0x7440 | byte_sel);
    return fmaf(__int_as_float(bits), (1.0f / 25.0f),
                -(8388608.0f * (1.0f / 25.0f)));
}

__global__ __launch_bounds__(NTHREADS, 5)
void ehd_fused_kernel(const float* __restrict__ x,
                      float* __restrict__ out)
{
    __shared__ u64 s_h[IT][36];   // horizontal 5-sums (16B-aligned even cols)

    const int tid  = threadIdx.x;
    const int lane = tid & 31;
    const int ox   = blockIdx.x * T;
    const int oy   = blockIdx.y * T;
    const int b    = blockIdx.z;

    const int r  = tid >> 3;          // index row within tile (0..31)
    const int c0 = (tid & 7) << 2;    // index col group (0,4,...,28)
    const int gx = ox + c0;           // global col of first px (mult of 4)
    const int gy = oy + r;            // global row of index px

    const float* xb = x + (size_t)b * (1024 * 1024);

    // ---- stage A: 3x6 input window; own quad via LDG.128, cols 4..5
    // borrowed from lane+1 via shfl (fallback LDG.64 at group edges) ----
    float w[3][6];
    if (ox + 34 <= 1024 && oy + 34 <= 1024) {
        // fast path (CTA-uniform condition -> warp-converged shfl)
#pragma unroll
        for (int j = 0; j < 3; j++) {
            const float* row = xb + (gy + j) * 1024 + gx;
            const float4 a = *(const float4*)row;       // gx multiple of 4
            w[j][0] = a.x; w[j][1] = a.y; w[j][2] = a.z; w[j][3] = a.w;
        }
        const bool edge = ((lane & 7) == 7);   // lane+1 is a different row
#pragma unroll
        for (int j = 0; j < 3; j++) {
            const float t0 = __shfl_down_sync(0xFFFFFFFFu, w[j][0], 1);
            const float t1 = __shfl_down_sync(0xFFFFFFFFu, w[j][1], 1);
            if (edge) {
                const float2 bb = *(const float2*)(xb + (gy + j) * 1024 + gx + 4);
                w[j][4] = bb.x; w[j][5] = bb.y;
            } else {
                w[j][4] = t0; w[j][5] = t1;
            }
        }
    } else {
        // slow path (edge tiles): per-element predicated, zero-fill OOB.
        // OOB zeros only feed index px whose outputs are clipped below.
#pragma unroll
        for (int j = 0; j < 3; j++) {
            const int yy = gy + j;
            const bool yv = (yy < 1024);
            const float* row = xb + yy * 1024 + gx;
#pragma unroll
            for (int k = 0; k < 6; k++)
                w[j][k] = (yv && (gx + k < 1024)) ? row[k] : 0.0f;
        }
    }

    // ---- stage B: conv (8 filters) + argmax + threshold, 4 horizontal px ----
    float best[4];
    int   bi[4];
#pragma unroll
    for (int q = 0; q < 4; q++) { best[q] = -3.4e38f; bi[q] = 0; }

#pragma unroll
    for (int f = 0; f < NOR; f++) {
        const float m0 = c_masks[f * 9 + 0], m1 = c_masks[f * 9 + 1], m2 = c_masks[f * 9 + 2];
        const float m3 = c_masks[f * 9 + 3], m4 = c_masks[f * 9 + 4], m5 = c_masks[f * 9 + 5];
        const float m6 = c_masks[f * 9 + 6], m7 = c_masks[f * 9 + 7], m8 = c_masks[f * 9 + 8];
#pragma unroll
        for (int q = 0; q < 4; q++) {
            float acc = w[0][q] * m0;
            acc = fmaf(w[0][q + 1], m1, acc);
            acc = fmaf(w[0][q + 2], m2, acc);
            acc = fmaf(w[1][q    ], m3, acc);
            acc = fmaf(w[1][q + 1], m4, acc);
            acc = fmaf(w[1][q + 2], m5, acc);
            acc = fmaf(w[2][q    ], m6, acc);
            acc = fmaf(w[2][q + 1], m7, acc);
            acc = fmaf(w[2][q + 2], m8, acc);
            // strict > keeps FIRST max (jnp.argmax tie-break)
            if (acc > best[q]) { best[q] = acc; bi[q] = f; }
        }
    }

    // byte-packed one-hot: bins 0..7 -> one byte of a u64; bin 8 implicit
    u64 oh[4];
#pragma unroll
    for (int q = 0; q < 4; q++) {
        const int idx = (best[q] < THRESH) ? NOR : bi[q];
        oh[q] = (idx < NOR) ? (1ULL << (idx << 3)) : 0ULL;
    }

    // ---- stage C: horizontal 5-tap via shfl (neighbor quad = lane+1) ----
    const bool has_nbr = ((lane & 7) != 7);
    u64 n[4];
#pragma unroll
    for (int q = 0; q < 4; q++) {
        const u64 t = __shfl_down_sync(0xFFFFFFFFu, oh[q], 1);
        n[q] = has_nbr ? t : 0ULL;
    }
    const u64 h0 = oh[0] + oh[1] + oh[2] + oh[3] + n[0];
    const u64 h1 = h0 - oh[0] + n[1];
    const u64 h2 = h1 - oh[1] + n[2];
    const u64 h3 = h2 - oh[2] + n[3];
    {
        ulonglong2* dst = (ulonglong2*)&s_h[r][c0];
        dst[0] = make_ulonglong2(h0, h1);
        dst[1] = make_ulonglong2(h2, h3);
    }
    __syncthreads();   // the only barrier

    // ---- stage D: vertical 5-tap on column pairs, unpack, float2 stores ----
    const size_t plane = (size_t)OUT_H * OUT_W;
    float* ob = out + (size_t)b * NBINS * plane;
#pragma unroll
    for (int it = 0; it < 2; it++) {
        const int u = tid + it * NTHREADS;
        if (u < 14 * T) {
            const int rr = u / 14;
            const int cc = (u - rr * 14) * 2;
            const int oyy = oy + rr, oxx = ox + cc;
            if (oyy < OUT_H && oxx + 1 < OUT_W) {
                ulonglong2 q0 = *(const ulonglong2*)&s_h[rr    ][cc];
                ulonglong2 q1 = *(const ulonglong2*)&s_h[rr + 1][cc];
                ulonglong2 q2 = *(const ulonglong2*)&s_h[rr + 2][cc];
                ulonglong2 q3 = *(const ulonglong2*)&s_h[rr + 3][cc];
                ulonglong2 q4 = *(const ulonglong2*)&s_h[rr + 4][cc];
                const u64 v0 = q0.x + q1.x + q2.x + q3.x + q4.x;
                const u64 v1 = q0.y + q1.y + q2.y + q3.y + q4.y;
                const unsigned lo0 = (unsigned)v0, hi0 = (unsigned)(v0 >> 32);
                const unsigned lo1 = (unsigned)v1, hi1 = (unsigned)(v1 >> 32);

                float* p = ob + (size_t)oyy * OUT_W + oxx;
#pragma unroll
                for (int bin = 0; bin < 8; bin++) {
                    float2 v;
                    v.x = cnt_scale((bin < 4) ? lo0 : hi0, bin & 3);
                    v.y = cnt_scale((bin < 4) ? lo1 : hi1, bin & 3);
                    *(float2*)(p + (size_t)bin * plane) = v;
                }
                // bin 8 = 25 - sum of the other 8 counts
                const unsigned s0 = __dp4a(lo0, 0x01010101u, __dp4a(hi0, 0x01010101u, 0u));
                const unsigned s1 = __dp4a(lo1, 0x01010101u, __dp4a(hi1, 0x01010101u, 0u));
                float2 v8;
                v8.x = cnt_scale(25u - s0, 0);
                v8.y = cnt_scale(25u - s1, 0);
                *(float2*)(p + (size_t)8 * plane) = v8;
            }
        }
    }
}

extern "C" void kernel_launch(void* const* d_in, const int* in_sizes, int n_in,
                              void* d_out, int out_size)
{
    const float* x     = (const float*)d_in[0];   // [B,1,1024,1024]
    const float* masks = (const float*)d_in[1];   // [8,1,3,3]
    float* out = (float*)d_out;                   // [B,9,1018,1018]

    const int batch = in_sizes[0] / (1024 * 1024);

    // masks -> constant bank (device-to-device async copy: graph-capturable)
    cudaMemcpyToSymbolAsync(c_masks, masks, NOR * 9 * sizeof(float), 0,
                            cudaMemcpyDeviceToDevice);

    dim3 grid((OUT_W + T - 1) / T, (OUT_H + T - 1) / T, batch);
    ehd_fused_kernel<<<grid, NTHREADS>>>(x, out);
}